// round 14
// baseline (speedup 1.0000x reference)
#include <cuda_runtime.h>
#include <cuda_bf16.h>

// Problem constants
#define Bc 2
#define Lc 2048
#define Kc 30
#define Hc 128
#define RBFN 16
#define NFN 267   // node features
#define NFE 121   // edge features
#define QPB 8     // knn queries per block (one per warp)

// Scratch (device globals: allocation-free rule)
__device__ int   g_eidx[Bc*Lc*Kc];
__device__ float g_O[Bc*Lc*9];
__device__ int   g_last[Bc];
// Edge weights prepacked as per-lane mma fragments: [kt(8)][ntg(16)][lane(32)] uint2
__device__ uint2 g_Wh[4096];
__device__ uint2 g_Wl[4096];

struct F3 { float x, y, z; };
__device__ __forceinline__ F3 f3sub(F3 a, F3 b){ return {a.x-b.x, a.y-b.y, a.z-b.z}; }
__device__ __forceinline__ float dot3(F3 a, F3 b){ return a.x*b.x + a.y*b.y + a.z*b.z; }
__device__ __forceinline__ F3 cross3(F3 a, F3 b){
    return { a.y*b.z - a.z*b.y, a.z*b.x - a.x*b.z, a.x*b.y - a.y*b.x };
}
__device__ __forceinline__ F3 norm3v(F3 a){
    float n = sqrtf(dot3(a,a));
    float d = fmaxf(n, 1e-12f);
    return { a.x/d, a.y/d, a.z/d };
}
__device__ __forceinline__ F3 ld3(const float* p){ return { p[0], p[1], p[2] }; }
__device__ __forceinline__ float sgnf(float x){ return (x > 0.f) ? 1.f : ((x < 0.f) ? -1.f : 0.f); }

// packed f32x2 helpers (node kernel)
__device__ __forceinline__ unsigned long long pack2(float a, float b){
    unsigned long long r;
    asm("mov.b64 %0, {%1, %2};" : "=l"(r) : "f"(a), "f"(b));
    return r;
}
__device__ __forceinline__ void unpack2(unsigned long long v, float& a, float& b){
    asm("mov.b64 {%0, %1}, %2;" : "=f"(a), "=f"(b) : "l"(v));
}
__device__ __forceinline__ void pfma(unsigned long long& acc, unsigned long long a, unsigned long long b){
    asm("fma.rn.f32x2 %0, %1, %2, %0;" : "+l"(acc) : "l"(a), "l"(b));
}

__device__ __forceinline__ unsigned smem_u32(const void* p){
    unsigned a;
    asm("{ .reg .u64 t; cvta.to.shared.u64 t, %1; cvt.u32.u64 %0, t; }" : "=r"(a) : "l"(p));
    return a;
}
__device__ __forceinline__ unsigned pack_bf2(float a, float b){
    __nv_bfloat162 t = __floats2bfloat162_rn(a, b);
    return *reinterpret_cast<unsigned*>(&t);
}
__device__ __forceinline__ void mma_bf16(float* d, unsigned a0, unsigned a1, unsigned a2, unsigned a3,
                                         unsigned b0, unsigned b1){
    asm volatile("mma.sync.aligned.m16n8k16.row.col.f32.bf16.bf16.f32 "
        "{%0,%1,%2,%3}, {%4,%5,%6,%7}, {%8,%9}, {%0,%1,%2,%3};"
        : "+f"(d[0]), "+f"(d[1]), "+f"(d[2]), "+f"(d[3])
        : "r"(a0), "r"(a1), "r"(a2), "r"(a3), "r"(b0), "r"(b1));
}
__device__ __forceinline__ void ldm4(unsigned* a, unsigned addr){
    asm volatile("ldmatrix.sync.aligned.m8n8.x4.shared.b16 {%0,%1,%2,%3}, [%4];"
        : "=r"(a[0]), "=r"(a[1]), "=r"(a[2]), "=r"(a[3]) : "r"(addr));
}

// xyz layout: [B][L][6][3] row-major
__device__ __forceinline__ const float* atom_ptr(const float* xyz, int b, int l, int a){
    return xyz + (((size_t)(b*Lc + l))*6 + a)*3;
}
__device__ __forceinline__ F3 ldP(const float* xyz, int b, int t){
    int r = t / 3, a = t - 3*r;
    return ld3(atom_ptr(xyz, b, r, a));
}

// ---------------------------------------------------------------------------
// prep: frames O + last index + edge-weight bf16 hi/lo fragment prepack
// ---------------------------------------------------------------------------
__global__ void prep_kernel(const float* __restrict__ xyz, const float* __restrict__ mask,
                            const float* __restrict__ ew){
    int gid = blockIdx.x*blockDim.x + threadIdx.x;
    if (blockIdx.x == 0 && threadIdx.x < 64){
        int b = threadIdx.x >> 5, lane = threadIdx.x & 31;
        float s = 0.f;
        for (int m = lane; m < Lc; m += 32) s += mask[b*Lc + m];
        #pragma unroll
        for (int o = 16; o; o >>= 1) s += __shfl_xor_sync(0xffffffffu, s, o);
        if (lane == 0) g_last[b] = (int)s - 1;
    }
    if (gid < Bc*Lc){
        int b = gid / Lc, l = gid % Lc;
        float o[9] = {0,0,0,0,0,0,0,0,0};
        if (l >= 1 && l <= Lc-3){
            F3 cm = ld3(atom_ptr(xyz,b,l-1,1));
            F3 c0 = ld3(atom_ptr(xyz,b,l  ,1));
            F3 cp = ld3(atom_ptr(xyz,b,l+1,1));
            F3 u2 = norm3v(f3sub(c0,cm));
            F3 u1 = norm3v(f3sub(cp,c0));
            F3 o1 = norm3v(f3sub(u2,u1));
            F3 n2 = norm3v(cross3(u2,u1));
            F3 o3 = cross3(o1,n2);
            o[0]=o1.x; o[1]=o1.y; o[2]=o1.z;
            o[3]=n2.x; o[4]=n2.y; o[5]=n2.z;
            o[6]=o3.x; o[7]=o3.y; o[8]=o3.z;
        }
        #pragma unroll
        for (int q = 0; q < 9; q++) g_O[(size_t)gid*9 + q] = o[q];
    }
    // W fragment prepack: gid = kt*512 + ntg*32 + lane
    if (gid < 4096){
        int lane = gid & 31;
        int ntg  = (gid >> 5) & 15;
        int kt   = gid >> 9;
        int g = lane >> 2, tg = lane & 3;
        int n = ntg*8 + g;
        int k0 = kt*16 + 2*tg;
        float w00 = (k0   < NFE) ? ew[(k0  )*Hc + n] : 0.f;
        float w01 = (k0+1 < NFE) ? ew[(k0+1)*Hc + n] : 0.f;
        float w10 = (k0+8 < NFE) ? ew[(k0+8)*Hc + n] : 0.f;
        float w11 = (k0+9 < NFE) ? ew[(k0+9)*Hc + n] : 0.f;
        float h00 = __bfloat162float(__float2bfloat16(w00));
        float h01 = __bfloat162float(__float2bfloat16(w01));
        float h10 = __bfloat162float(__float2bfloat16(w10));
        float h11 = __bfloat162float(__float2bfloat16(w11));
        g_Wh[gid] = make_uint2(pack_bf2(h00, h01), pack_bf2(h10, h11));
        g_Wl[gid] = make_uint2(pack_bf2(w00-h00, w01-h01), pack_bf2(w10-h10, w11-h11));
    }
}

// ---------------------------------------------------------------------------
// KNN: one warp per query, stored per-warp distance row, SoA coords (R13).
// ---------------------------------------------------------------------------
__device__ __forceinline__ void knn_insert3(float d, int j,
    float& v1, int& i1, float& v2, int& i2, float& v3, int& i3){
    if (d < v3){
        if (d < v2){
            if (d < v1){ v3=v2; i3=i2; v2=v1; i2=i1; v1=d; i1=j; }
            else       { v3=v2; i3=i2; v2=d;  i2=j; }
        } else         { v3=d;  i3=j; }
    }
}

__global__ void __launch_bounds__(256) knn_kernel(const float* __restrict__ xyz,
                                                  const float* __restrict__ mask,
                                                  float* __restrict__ out_eidx){
    extern __shared__ float dyns[];
    float* sx  = dyns;              // Lc
    float* sy  = sx + Lc;           // Lc
    float* sz  = sy + Lc;           // Lc
    float* smk = sz + Lc;           // Lc
    float* sdall = smk + Lc;        // QPB*Lc

    int tid = threadIdx.x;
    int w = tid >> 5, lane = tid & 31;
    int b = blockIdx.y;
    int i = blockIdx.x*QPB + w;

    for (int j = tid; j < Lc; j += 256){
        const float* p = atom_ptr(xyz, b, j, 1);
        sx[j] = p[0]; sy[j] = p[1]; sz[j] = p[2];
        smk[j] = mask[b*Lc + j];
    }
    __syncthreads();

    float* sdr = sdall + w*Lc;
    float xi = sx[i], yi = sy[i], zi = sz[i];
    float mi = smk[i];

    float dmax = -1e30f;
    #pragma unroll 4
    for (int m = 0; m < 64; m++){
        int j = lane + 32*m;
        float dx = __fadd_rn(sx[j], -xi);
        float dy = __fadd_rn(sy[j], -yi);
        float dz = __fadd_rn(sz[j], -zi);
        float s  = __fadd_rn(__fadd_rn(__fmul_rn(dx,dx), __fmul_rn(dy,dy)), __fmul_rn(dz,dz));
        float D  = __fmul_rn(__fmul_rn(smk[j], mi), __fsqrt_rn(__fadd_rn(s, 1e-6f)));
        sdr[j] = D;
        dmax = fmaxf(dmax, D);
    }
    {
        unsigned mb = __reduce_max_sync(0xffffffffu, __float_as_uint(dmax));
        dmax = __uint_as_float(mb);
    }

    float v1 = 1e38f, v2 = 1e38f, v3 = 1e38f;
    int   i1 = 0x7fffffff, i2 = 0x7fffffff, i3 = 0x7fffffff;
    #pragma unroll 4
    for (int m = 0; m < 64; m++){
        int j = lane + 32*m;
        float m2 = __fmul_rn(smk[j], mi);
        float d = __fadd_rn(sdr[j], __fmul_rn(__fadd_rn(1.0f, -m2), dmax));
        sdr[j] = d;
        knn_insert3(d, j, v1, i1, v2, i2, v3, i3);
    }

    size_t obase = (size_t)(b*Lc + i)*Kc;
    for (int it = 0; it < Kc; it++){
        unsigned myb = __float_as_uint(v1);
        unsigned kb = __reduce_min_sync(0xffffffffu, myb);
        unsigned cand = (myb == kb) ? (unsigned)i1 : 0xffffffffu;
        unsigned ib = __reduce_min_sync(0xffffffffu, cand);
        if (lane == 0){
            g_eidx[obase + it] = (int)ib;
            out_eidx[obase + it] = (float)ib;
        }
        if (myb == kb && (unsigned)i1 == ib){
            sdr[i1] = 1e38f;
            v1 = v2; i1 = i2;
            v2 = v3; i2 = i3;
            v3 = 1e38f; i3 = 0x7fffffff;
            if (v1 == 1e38f && it < Kc-1){
                v1 = v2 = v3 = 1e38f; i1 = i2 = i3 = 0x7fffffff;
                #pragma unroll 8
                for (int m = 0; m < 64; m++){
                    int j = lane + 32*m;
                    float d = sdr[j];
                    knn_insert3(d, j, v1, i1, v2, i2, v3, i3);
                }
            }
        }
    }
}

// ---------------------------------------------------------------------------
// Node (exact R8 version — warp-coalesced scalar weight loads)
// ---------------------------------------------------------------------------
__global__ void __launch_bounds__(128) node_kernel(const float* __restrict__ xyz,
                            const float* __restrict__ nw, const float* __restrict__ nb,
                            const float* __restrict__ lg, const float* __restrict__ lb,
                            float* __restrict__ out){
    __shared__ __align__(16) float ft[NFN*4];
    __shared__ float outs[4][Hc+1];
    __shared__ float smu[4], srs[4];

    int tid = threadIdx.x;
    int warp = tid >> 5, lane = tid & 31;
    int gid = blockIdx.x*4 + warp;
    int b = gid / Lc, l = gid % Lc;

    {
        const float* ap = xyz + (size_t)gid*18;
        F3 A0 = ld3(ap+0), A1 = ld3(ap+3), A2 = ld3(ap+6);
        F3 A3 = ld3(ap+9), A4 = ld3(ap+12), A5 = ld3(ap+15);
        F3 u = norm3v(f3sub(A0,A1));
        F3 v = norm3v(f3sub(A1,A2));
        F3 fb = norm3v(f3sub(u,v));
        F3 fn = norm3v(cross3(u,v));
        F3 fc = cross3(fb,fn);

        if (lane < 15){
            const int sel[5] = {0,2,3,4,5};
            int a = lane/3, d = lane%3;
            F3 Aa = (sel[a]==0)?A0:((sel[a]==2)?A2:((sel[a]==3)?A3:((sel[a]==4)?A4:A5)));
            F3 t = norm3v(f3sub(Aa, A1));
            F3 col = (d==0)?fb:((d==1)?fn:fc);
            ft[lane*4 + warp] = dot3(t, col);

            const int r0[15] = {0,0,0,0,0,1,1,1,1,2,2,2,3,3,4};
            const int r1[15] = {1,2,3,4,5,2,3,4,5,3,4,5,4,5,5};
            F3 P[6] = {A0,A1,A2,A3,A4,A5};
            F3 dd = f3sub(P[r0[lane]], P[r1[lane]]);
            float Dn = sqrtf(dot3(dd,dd));
            #pragma unroll
            for (int q = 0; q < RBFN; q++){
                float t2 = (Dn - (float)q*(20.0f/15.0f)) * 0.8f;
                ft[(27 + lane*RBFN + q)*4 + warp] = __expf(-t2*t2);
            }
        } else if (lane < 18){
            int s = lane - 15;
            int p = 3*l + s;
            float Dd = 0.f, Db = 0.f;
            if (p >= 1 && p <= 3*Lc - 3){
                int raw = p - 1;
                F3 P0 = ldP(xyz,b,raw),   P1 = ldP(xyz,b,raw+1);
                F3 P2 = ldP(xyz,b,raw+2), P3 = ldP(xyz,b,raw+3);
                F3 u2 = norm3v(f3sub(P1,P0));
                F3 u1 = norm3v(f3sub(P2,P1));
                F3 u0 = norm3v(f3sub(P3,P2));
                F3 n2 = norm3v(cross3(u2,u1));
                F3 n1 = norm3v(cross3(u1,u0));
                float cd = fminf(fmaxf(dot3(n2,n1), -1.f + 1e-7f), 1.f - 1e-7f);
                Dd = sgnf(dot3(u2,n1)) * acosf(cd);
                float cb = fminf(fmaxf(dot3(u2,u1), -1.f + 1e-7f), 1.f - 1e-7f);
                Db = acosf(cb);
            }
            float cDd = cosf(Dd), sDd = sinf(Dd), cDb = cosf(Db), sDb = sinf(Db);
            if (l == g_last[b]){ cDd = 0.f; sDd = 0.f; cDb = 0.f; sDb = 0.f; }
            ft[(15 + s)*4 + warp] = cDd;
            ft[(18 + s)*4 + warp] = sDd;
            ft[(21 + s)*4 + warp] = cDb;
            ft[(24 + s)*4 + warp] = sDb;
        }
    }
    __syncthreads();

    int h = tid;
    float bias = nb[h];
    unsigned long long acc0 = pack2(bias, bias);
    unsigned long long acc1 = pack2(bias, bias);
    const ulonglong2* ftu = reinterpret_cast<const ulonglong2*>(ft);
    for (int f = 0; f < NFN; f++){
        float wf = __ldg(nw + f*Hc + h);
        unsigned long long w2 = pack2(wf, wf);
        ulonglong2 a = ftu[f];
        pfma(acc0, a.x, w2);
        pfma(acc1, a.y, w2);
    }
    float y0,y1,y2,y3;
    unpack2(acc0, y0, y1);
    unpack2(acc1, y2, y3);
    outs[0][h] = y0; outs[1][h] = y1; outs[2][h] = y2; outs[3][h] = y3;
    __syncthreads();

    if (tid < 4){
        float s = 0.f;
        for (int q = 0; q < Hc; q++) s += outs[tid][q];
        float mu = s / (float)Hc;
        float s2 = 0.f;
        for (int q = 0; q < Hc; q++){ float d = outs[tid][q] - mu; s2 += d*d; }
        smu[tid] = mu;
        srs[tid] = 1.f / sqrtf(s2 / (float)Hc + 1e-5f);
    }
    __syncthreads();

    int row0 = blockIdx.x*4;
    float gh = lg[h], bh = lb[h];
    #pragma unroll
    for (int r = 0; r < 4; r++){
        out[(size_t)(row0 + r)*Hc + h] = (outs[r][h] - smu[r])*srs[r]*gh + bh;
    }
}

// ---------------------------------------------------------------------------
// Edge via mma.sync bf16 3-pass split — 256 threads/CTA, 8 warps.
// Warp w: rows mt in {(w>>2)*2, +1} (16 rows each), cols ntg in [(w&3)*4, +4).
// acc = 2x4x4 = 32 fp32/thread. Feature gen: 4-way sub split over 240 threads.
// ---------------------------------------------------------------------------
#define A_STRIDE 136                 // bf16 elems per row (272 bytes)
#define A_BYTES  (64*A_STRIDE*2)     // 17408 per array

__device__ __forceinline__ void edge_wAB(unsigned short* Ah, unsigned short* Al, int idx, float v){
    __nv_bfloat16 h = __float2bfloat16(v);
    Ah[idx] = *reinterpret_cast<unsigned short*>(&h);
    __nv_bfloat16 lo = __float2bfloat16(v - __bfloat162float(h));
    Al[idx] = *reinterpret_cast<unsigned short*>(&lo);
}

__global__ void __launch_bounds__(256, 2) edge_kernel(const float* __restrict__ xyz,
                            const float* __restrict__ eb,
                            const float* __restrict__ lg, const float* __restrict__ lb,
                            float* __restrict__ out){
    __shared__ __align__(16) unsigned char sA[2*A_BYTES];   // Ahi | Alo ; aliased by LN staging
    __shared__ float seb[Hc];
    __shared__ float smu[64], srs[64];

    int tid = threadIdx.x;
    int warp = tid >> 5, lane = tid & 31;
    int b = blockIdx.y;
    int l0 = blockIdx.x*2;
    int base0 = b*Lc + l0;

    unsigned short* Ah = reinterpret_cast<unsigned short*>(sA);
    unsigned short* Al = reinterpret_cast<unsigned short*>(sA + A_BYTES);

    {
        uint4* p = reinterpret_cast<uint4*>(sA);
        for (int i = tid; i < (2*A_BYTES)/16; i += 256) p[i] = make_uint4(0,0,0,0);
    }
    if (tid < Hc) seb[tid] = eb[tid];
    __syncthreads();

    // ---- feature generation: 4 threads per row (sub 0..3), rows 0..59 ----
    if (tid < 240){
        int r = tid >> 2, sub = tid & 3;
        int res = r / 30;
        int base = base0 + res;
        int j = g_eidx[(size_t)base*Kc + (r - 30*res)];
        const float* api = xyz + (size_t)base*18;
        const float* apj = xyz + (size_t)(b*Lc + j)*18;
        F3 Ca = ld3(api + 3);
        int ro = r*A_STRIDE;

        if (sub <= 1){
            F3 Ai0 = ld3(api+0), Ai2 = ld3(api+6);
            F3 u = norm3v(f3sub(Ai0, Ca));
            F3 v = norm3v(f3sub(Ca, Ai2));
            F3 fb = norm3v(f3sub(u,v));
            F3 fn = norm3v(cross3(u,v));
            F3 fc = cross3(fb,fn);
            int a0 = sub*3;
            #pragma unroll
            for (int a = a0; a < a0+3; a++){
                F3 tv = norm3v(f3sub(ld3(apj + a*3), Ca));
                edge_wAB(Ah, Al, ro + a*3+0, dot3(tv, fb));
                edge_wAB(Ah, Al, ro + a*3+1, dot3(tv, fn));
                edge_wAB(Ah, Al, ro + a*3+2, dot3(tv, fc));
            }
            {
                int a = sub;
                F3 d = f3sub(ld3(apj + a*3), Ca);
                float De = sqrtf(dot3(d,d));
                #pragma unroll
                for (int q = 0; q < RBFN; q++){
                    float t2 = (De - (float)q*(20.0f/15.0f))*0.8f;
                    edge_wAB(Ah, Al, ro + 25 + a*RBFN + q, __expf(-t2*t2));
                }
            }
        } else if (sub == 2){
            float Om[9], On[9];
            #pragma unroll
            for (int q = 0; q < 9; q++) Om[q] = g_O[(size_t)base*9 + q];
            #pragma unroll
            for (int q = 0; q < 9; q++) On[q] = g_O[(size_t)(b*Lc + j)*9 + q];
            F3 Cj = ld3(apj + 3);
            F3 dX = f3sub(Cj, Ca);
            float d0 = Om[0]*dX.x + Om[1]*dX.y + Om[2]*dX.z;
            float d1 = Om[3]*dX.x + Om[4]*dX.y + Om[5]*dX.z;
            float d2 = Om[6]*dX.x + Om[7]*dX.y + Om[8]*dX.z;
            float nn = sqrtf(d0*d0 + d1*d1 + d2*d2);
            float inv = 1.f / fmaxf(nn, 1e-12f);
            edge_wAB(Ah, Al, ro + 18, d0*inv);
            edge_wAB(Ah, Al, ro + 19, d1*inv);
            edge_wAB(Ah, Al, ro + 20, d2*inv);
            float R[3][3];
            #pragma unroll
            for (int ii = 0; ii < 3; ii++)
                #pragma unroll
                for (int m = 0; m < 3; m++)
                    R[ii][m] = Om[0*3+ii]*On[0*3+m] + Om[1*3+ii]*On[1*3+m] + Om[2*3+ii]*On[2*3+m];
            float Rxx = R[0][0], Ryy = R[1][1], Rzz = R[2][2];
            float mx = 0.5f*sqrtf(fabsf(1.f + Rxx - Ryy - Rzz));
            float my = 0.5f*sqrtf(fabsf(1.f - Rxx + Ryy - Rzz));
            float mz = 0.5f*sqrtf(fabsf(1.f - Rxx - Ryy + Rzz));
            float qx = sgnf(R[2][1] - R[1][2]) * mx;
            float qy = sgnf(R[0][2] - R[2][0]) * my;
            float qz = sgnf(R[1][0] - R[0][1]) * mz;
            float qw = sqrtf(fmaxf(1.f + Rxx + Ryy + Rzz, 0.f)) * 0.5f;
            float qn = sqrtf(qx*qx + qy*qy + qz*qz + qw*qw);
            float qi = 1.f / fmaxf(qn, 1e-12f);
            edge_wAB(Ah, Al, ro + 21, qx*qi);
            edge_wAB(Ah, Al, ro + 22, qy*qi);
            edge_wAB(Ah, Al, ro + 23, qz*qi);
            edge_wAB(Ah, Al, ro + 24, qw*qi);
            #pragma unroll
            for (int a = 2; a <= 3; a++){
                F3 d = f3sub(ld3(apj + a*3), Ca);
                float De = sqrtf(dot3(d,d));
                #pragma unroll
                for (int q = 0; q < RBFN; q++){
                    float t2 = (De - (float)q*(20.0f/15.0f))*0.8f;
                    edge_wAB(Ah, Al, ro + 25 + a*RBFN + q, __expf(-t2*t2));
                }
            }
        } else {
            #pragma unroll
            for (int a = 4; a <= 5; a++){
                F3 d = f3sub(ld3(apj + a*3), Ca);
                float De = sqrtf(dot3(d,d));
                #pragma unroll
                for (int q = 0; q < RBFN; q++){
                    float t2 = (De - (float)q*(20.0f/15.0f))*0.8f;
                    edge_wAB(Ah, Al, ro + 25 + a*RBFN + q, __expf(-t2*t2));
                }
            }
        }
    }
    __syncthreads();

    // ---- MMA: warp (mtb = (w>>2)*2 rows x 2, ntq = w&3 cols x 4) ----
    int mtb = (warp >> 2)*2;
    int ntq = warp & 3;
    float acc[2][4][4];
    #pragma unroll
    for (int mi = 0; mi < 2; mi++)
        #pragma unroll
        for (int nt = 0; nt < 4; nt++)
            #pragma unroll
            for (int q = 0; q < 4; q++) acc[mi][nt][q] = 0.f;

    unsigned aHiB = smem_u32(Ah);
    unsigned aLoB = smem_u32(Al);
    unsigned rowterm = (lane & 7) + ((lane >> 3) & 1)*8;
    unsigned colterm = ((lane >> 4) & 1)*16;   // bytes

    #pragma unroll
    for (int kt = 0; kt < 8; kt++){
        uint2 bh[4], bl[4];
        #pragma unroll
        for (int nt = 0; nt < 4; nt++){
            int idx = (kt*16 + ntq*4 + nt)*32 + lane;
            bh[nt] = __ldg(g_Wh + idx);
            bl[nt] = __ldg(g_Wl + idx);
        }
        #pragma unroll
        for (int mi = 0; mi < 2; mi++){
            int mt = mtb + mi;
            unsigned off = (mt*16 + rowterm)*(A_STRIDE*2) + (unsigned)kt*32 + colterm;
            unsigned ah[4], al[4];
            ldm4(ah, aHiB + off);
            ldm4(al, aLoB + off);
            #pragma unroll
            for (int nt = 0; nt < 4; nt++){
                mma_bf16(acc[mi][nt], ah[0], ah[1], ah[2], ah[3], bh[nt].x, bh[nt].y);
                mma_bf16(acc[mi][nt], ah[0], ah[1], ah[2], ah[3], bl[nt].x, bl[nt].y);
                mma_bf16(acc[mi][nt], al[0], al[1], al[2], al[3], bh[nt].x, bh[nt].y);
            }
        }
    }
    __syncthreads();   // all ldmatrix reads done -> safe to overwrite sA (alias)

    // ---- stage D + bias into LN buffer (aliases sA) ----
    float* lnb = reinterpret_cast<float*>(sA);   // [64][130]
    int g = lane >> 2, tg = lane & 3;
    #pragma unroll
    for (int mi = 0; mi < 2; mi++){
        int mt = mtb + mi;
        #pragma unroll
        for (int nt = 0; nt < 4; nt++){
            int row = mt*16 + g;
            int col = (ntq*4 + nt)*8 + 2*tg;
            float e0 = seb[col], e1 = seb[col+1];
            *reinterpret_cast<unsigned long long*>(lnb + row*130 + col) =
                pack2(acc[mi][nt][0] + e0, acc[mi][nt][1] + e1);
            *reinterpret_cast<unsigned long long*>(lnb + (row+8)*130 + col) =
                pack2(acc[mi][nt][2] + e0, acc[mi][nt][3] + e1);
        }
    }
    __syncthreads();

    if (tid < 60){
        float s = 0.f;
        for (int q = 0; q < Hc; q++) s += lnb[tid*130 + q];
        float mu = s / (float)Hc;
        float s2 = 0.f;
        for (int q = 0; q < Hc; q++){ float d = lnb[tid*130 + q] - mu; s2 += d*d; }
        smu[tid] = mu;
        srs[tid] = 1.f / sqrtf(s2 / (float)Hc + 1e-5f);
    }
    __syncthreads();

    // ---- LN apply + writeback: thread = (residue G, column c) ----
    int G = tid >> 7, c = tid & 127;
    float gc = lg[c], bc = lb[c];
    size_t obase = ((size_t)(base0 + G)*Kc)*Hc;
    #pragma unroll 5
    for (int rr = 0; rr < Kc; rr++){
        int r = G*30 + rr;
        float mu = smu[r], rs = srs[r];
        out[obase + (size_t)rr*Hc + c] = (lnb[r*130 + c] - mu)*rs*gc + bc;
    }
}

// ---------------------------------------------------------------------------
extern "C" void kernel_launch(void* const* d_in, const int* in_sizes, int n_in,
                              void* d_out, int out_size){
    const float* xyz    = (const float*)d_in[0];
    const float* mask   = (const float*)d_in[1];
    const float* node_w = (const float*)d_in[2];
    const float* node_b = (const float*)d_in[3];
    const float* edge_w = (const float*)d_in[4];
    const float* edge_b = (const float*)d_in[5];
    const float* ln_ng  = (const float*)d_in[6];
    const float* ln_nb  = (const float*)d_in[7];
    const float* ln_eg  = (const float*)d_in[8];
    const float* ln_eb  = (const float*)d_in[9];

    float* out = (float*)d_out;
    float* out_node = out;
    float* out_edge = out + (size_t)Bc*Lc*Hc;
    float* out_eidx = out_edge + (size_t)Bc*Lc*Kc*Hc;

    const int knn_smem = (4*Lc + QPB*Lc) * (int)sizeof(float); // 96 KB
    cudaFuncSetAttribute(knn_kernel, cudaFuncAttributeMaxDynamicSharedMemorySize, knn_smem);

    prep_kernel<<<(Bc*Lc + 255)/256, 256>>>(xyz, mask, edge_w);
    knn_kernel<<<dim3(Lc/QPB, Bc), 256, knn_smem>>>(xyz, mask, out_eidx);
    node_kernel<<<(Bc*Lc)/4, 128>>>(xyz, node_w, node_b, ln_ng, ln_nb, out_node);
    edge_kernel<<<dim3(Lc/2, Bc), 256>>>(xyz, edge_b, ln_eg, ln_eb, out_edge);
}

// round 15
// speedup vs baseline: 1.2795x; 1.2795x over previous
#include <cuda_runtime.h>
#include <cuda_bf16.h>

// Problem constants
#define Bc 2
#define Lc 2048
#define Kc 30
#define Hc 128
#define RBFN 16
#define NFN 267   // node features
#define NFE 121   // edge features
#define QPB 8     // knn queries per block (one per warp)

// Scratch (device globals: allocation-free rule)
__device__ int   g_eidx[Bc*Lc*Kc];
__device__ float g_O[Bc*Lc*9];
__device__ int   g_last[Bc];
// Edge weights prepacked as per-lane mma fragments: [kt(8)][ntg(16)][lane(32)] uint2
__device__ uint2 g_Wh[4096];
__device__ uint2 g_Wl[4096];

struct F3 { float x, y, z; };
__device__ __forceinline__ F3 f3sub(F3 a, F3 b){ return {a.x-b.x, a.y-b.y, a.z-b.z}; }
__device__ __forceinline__ float dot3(F3 a, F3 b){ return a.x*b.x + a.y*b.y + a.z*b.z; }
__device__ __forceinline__ F3 cross3(F3 a, F3 b){
    return { a.y*b.z - a.z*b.y, a.z*b.x - a.x*b.z, a.x*b.y - a.y*b.x };
}
__device__ __forceinline__ F3 norm3v(F3 a){
    float n = sqrtf(dot3(a,a));
    float d = fmaxf(n, 1e-12f);
    return { a.x/d, a.y/d, a.z/d };
}
__device__ __forceinline__ F3 ld3(const float* p){ return { p[0], p[1], p[2] }; }
__device__ __forceinline__ float sgnf(float x){ return (x > 0.f) ? 1.f : ((x < 0.f) ? -1.f : 0.f); }

// packed f32x2 helpers (node kernel)
__device__ __forceinline__ unsigned long long pack2(float a, float b){
    unsigned long long r;
    asm("mov.b64 %0, {%1, %2};" : "=l"(r) : "f"(a), "f"(b));
    return r;
}
__device__ __forceinline__ void unpack2(unsigned long long v, float& a, float& b){
    asm("mov.b64 {%0, %1}, %2;" : "=f"(a), "=f"(b) : "l"(v));
}
__device__ __forceinline__ void pfma(unsigned long long& acc, unsigned long long a, unsigned long long b){
    asm("fma.rn.f32x2 %0, %1, %2, %0;" : "+l"(acc) : "l"(a), "l"(b));
}

__device__ __forceinline__ unsigned smem_u32(const void* p){
    unsigned a;
    asm("{ .reg .u64 t; cvta.to.shared.u64 t, %1; cvt.u32.u64 %0, t; }" : "=r"(a) : "l"(p));
    return a;
}
__device__ __forceinline__ unsigned pack_bf2(float a, float b){
    __nv_bfloat162 t = __floats2bfloat162_rn(a, b);
    return *reinterpret_cast<unsigned*>(&t);
}
__device__ __forceinline__ void mma_bf16(float* d, unsigned a0, unsigned a1, unsigned a2, unsigned a3,
                                         unsigned b0, unsigned b1){
    asm volatile("mma.sync.aligned.m16n8k16.row.col.f32.bf16.bf16.f32 "
        "{%0,%1,%2,%3}, {%4,%5,%6,%7}, {%8,%9}, {%0,%1,%2,%3};"
        : "+f"(d[0]), "+f"(d[1]), "+f"(d[2]), "+f"(d[3])
        : "r"(a0), "r"(a1), "r"(a2), "r"(a3), "r"(b0), "r"(b1));
}
__device__ __forceinline__ void ldm4(unsigned* a, unsigned addr){
    asm volatile("ldmatrix.sync.aligned.m8n8.x4.shared.b16 {%0,%1,%2,%3}, [%4];"
        : "=r"(a[0]), "=r"(a[1]), "=r"(a[2]), "=r"(a[3]) : "r"(addr));
}

// xyz layout: [B][L][6][3] row-major
__device__ __forceinline__ const float* atom_ptr(const float* xyz, int b, int l, int a){
    return xyz + (((size_t)(b*Lc + l))*6 + a)*3;
}
__device__ __forceinline__ F3 ldP(const float* xyz, int b, int t){
    int r = t / 3, a = t - 3*r;
    return ld3(atom_ptr(xyz, b, r, a));
}

// ---------------------------------------------------------------------------
// prep: frames O + last index + edge-weight bf16 hi/lo fragment prepack
// ---------------------------------------------------------------------------
__global__ void prep_kernel(const float* __restrict__ xyz, const float* __restrict__ mask,
                            const float* __restrict__ ew){
    int gid = blockIdx.x*blockDim.x + threadIdx.x;
    if (blockIdx.x == 0 && threadIdx.x < 64){
        int b = threadIdx.x >> 5, lane = threadIdx.x & 31;
        float s = 0.f;
        for (int m = lane; m < Lc; m += 32) s += mask[b*Lc + m];
        #pragma unroll
        for (int o = 16; o; o >>= 1) s += __shfl_xor_sync(0xffffffffu, s, o);
        if (lane == 0) g_last[b] = (int)s - 1;
    }
    if (gid < Bc*Lc){
        int b = gid / Lc, l = gid % Lc;
        float o[9] = {0,0,0,0,0,0,0,0,0};
        if (l >= 1 && l <= Lc-3){
            F3 cm = ld3(atom_ptr(xyz,b,l-1,1));
            F3 c0 = ld3(atom_ptr(xyz,b,l  ,1));
            F3 cp = ld3(atom_ptr(xyz,b,l+1,1));
            F3 u2 = norm3v(f3sub(c0,cm));
            F3 u1 = norm3v(f3sub(cp,c0));
            F3 o1 = norm3v(f3sub(u2,u1));
            F3 n2 = norm3v(cross3(u2,u1));
            F3 o3 = cross3(o1,n2);
            o[0]=o1.x; o[1]=o1.y; o[2]=o1.z;
            o[3]=n2.x; o[4]=n2.y; o[5]=n2.z;
            o[6]=o3.x; o[7]=o3.y; o[8]=o3.z;
        }
        #pragma unroll
        for (int q = 0; q < 9; q++) g_O[(size_t)gid*9 + q] = o[q];
    }
    // W fragment prepack: gid = kt*512 + ntg*32 + lane
    if (gid < 4096){
        int lane = gid & 31;
        int ntg  = (gid >> 5) & 15;
        int kt   = gid >> 9;
        int g = lane >> 2, tg = lane & 3;
        int n = ntg*8 + g;
        int k0 = kt*16 + 2*tg;
        float w00 = (k0   < NFE) ? ew[(k0  )*Hc + n] : 0.f;
        float w01 = (k0+1 < NFE) ? ew[(k0+1)*Hc + n] : 0.f;
        float w10 = (k0+8 < NFE) ? ew[(k0+8)*Hc + n] : 0.f;
        float w11 = (k0+9 < NFE) ? ew[(k0+9)*Hc + n] : 0.f;
        float h00 = __bfloat162float(__float2bfloat16(w00));
        float h01 = __bfloat162float(__float2bfloat16(w01));
        float h10 = __bfloat162float(__float2bfloat16(w10));
        float h11 = __bfloat162float(__float2bfloat16(w11));
        g_Wh[gid] = make_uint2(pack_bf2(h00, h01), pack_bf2(h10, h11));
        g_Wl[gid] = make_uint2(pack_bf2(w00-h00, w01-h01), pack_bf2(w10-h10, w11-h11));
    }
}

// ---------------------------------------------------------------------------
// KNN: one warp per query, stored per-warp distance row, SoA coords (R13).
// ---------------------------------------------------------------------------
__device__ __forceinline__ void knn_insert3(float d, int j,
    float& v1, int& i1, float& v2, int& i2, float& v3, int& i3){
    if (d < v3){
        if (d < v2){
            if (d < v1){ v3=v2; i3=i2; v2=v1; i2=i1; v1=d; i1=j; }
            else       { v3=v2; i3=i2; v2=d;  i2=j; }
        } else         { v3=d;  i3=j; }
    }
}

__global__ void __launch_bounds__(256) knn_kernel(const float* __restrict__ xyz,
                                                  const float* __restrict__ mask,
                                                  float* __restrict__ out_eidx){
    extern __shared__ float dyns[];
    float* sx  = dyns;              // Lc
    float* sy  = sx + Lc;           // Lc
    float* sz  = sy + Lc;           // Lc
    float* smk = sz + Lc;           // Lc
    float* sdall = smk + Lc;        // QPB*Lc

    int tid = threadIdx.x;
    int w = tid >> 5, lane = tid & 31;
    int b = blockIdx.y;
    int i = blockIdx.x*QPB + w;

    for (int j = tid; j < Lc; j += 256){
        const float* p = atom_ptr(xyz, b, j, 1);
        sx[j] = p[0]; sy[j] = p[1]; sz[j] = p[2];
        smk[j] = mask[b*Lc + j];
    }
    __syncthreads();

    float* sdr = sdall + w*Lc;
    float xi = sx[i], yi = sy[i], zi = sz[i];
    float mi = smk[i];

    float dmax = -1e30f;
    #pragma unroll 4
    for (int m = 0; m < 64; m++){
        int j = lane + 32*m;
        float dx = __fadd_rn(sx[j], -xi);
        float dy = __fadd_rn(sy[j], -yi);
        float dz = __fadd_rn(sz[j], -zi);
        float s  = __fadd_rn(__fadd_rn(__fmul_rn(dx,dx), __fmul_rn(dy,dy)), __fmul_rn(dz,dz));
        float D  = __fmul_rn(__fmul_rn(smk[j], mi), __fsqrt_rn(__fadd_rn(s, 1e-6f)));
        sdr[j] = D;
        dmax = fmaxf(dmax, D);
    }
    {
        unsigned mb = __reduce_max_sync(0xffffffffu, __float_as_uint(dmax));
        dmax = __uint_as_float(mb);
    }

    float v1 = 1e38f, v2 = 1e38f, v3 = 1e38f;
    int   i1 = 0x7fffffff, i2 = 0x7fffffff, i3 = 0x7fffffff;
    #pragma unroll 4
    for (int m = 0; m < 64; m++){
        int j = lane + 32*m;
        float m2 = __fmul_rn(smk[j], mi);
        float d = __fadd_rn(sdr[j], __fmul_rn(__fadd_rn(1.0f, -m2), dmax));
        sdr[j] = d;
        knn_insert3(d, j, v1, i1, v2, i2, v3, i3);
    }

    size_t obase = (size_t)(b*Lc + i)*Kc;
    for (int it = 0; it < Kc; it++){
        unsigned myb = __float_as_uint(v1);
        unsigned kb = __reduce_min_sync(0xffffffffu, myb);
        unsigned cand = (myb == kb) ? (unsigned)i1 : 0xffffffffu;
        unsigned ib = __reduce_min_sync(0xffffffffu, cand);
        if (lane == 0){
            g_eidx[obase + it] = (int)ib;
            out_eidx[obase + it] = (float)ib;
        }
        if (myb == kb && (unsigned)i1 == ib){
            sdr[i1] = 1e38f;
            v1 = v2; i1 = i2;
            v2 = v3; i2 = i3;
            v3 = 1e38f; i3 = 0x7fffffff;
            if (v1 == 1e38f && it < Kc-1){
                v1 = v2 = v3 = 1e38f; i1 = i2 = i3 = 0x7fffffff;
                #pragma unroll 8
                for (int m = 0; m < 64; m++){
                    int j = lane + 32*m;
                    float d = sdr[j];
                    knn_insert3(d, j, v1, i1, v2, i2, v3, i3);
                }
            }
        }
    }
}

// ---------------------------------------------------------------------------
// Node (exact R8 version — warp-coalesced scalar weight loads)
// ---------------------------------------------------------------------------
__global__ void __launch_bounds__(128) node_kernel(const float* __restrict__ xyz,
                            const float* __restrict__ nw, const float* __restrict__ nb,
                            const float* __restrict__ lg, const float* __restrict__ lb,
                            float* __restrict__ out){
    __shared__ __align__(16) float ft[NFN*4];
    __shared__ float outs[4][Hc+1];
    __shared__ float smu[4], srs[4];

    int tid = threadIdx.x;
    int warp = tid >> 5, lane = tid & 31;
    int gid = blockIdx.x*4 + warp;
    int b = gid / Lc, l = gid % Lc;

    {
        const float* ap = xyz + (size_t)gid*18;
        F3 A0 = ld3(ap+0), A1 = ld3(ap+3), A2 = ld3(ap+6);
        F3 A3 = ld3(ap+9), A4 = ld3(ap+12), A5 = ld3(ap+15);
        F3 u = norm3v(f3sub(A0,A1));
        F3 v = norm3v(f3sub(A1,A2));
        F3 fb = norm3v(f3sub(u,v));
        F3 fn = norm3v(cross3(u,v));
        F3 fc = cross3(fb,fn);

        if (lane < 15){
            const int sel[5] = {0,2,3,4,5};
            int a = lane/3, d = lane%3;
            F3 Aa = (sel[a]==0)?A0:((sel[a]==2)?A2:((sel[a]==3)?A3:((sel[a]==4)?A4:A5)));
            F3 t = norm3v(f3sub(Aa, A1));
            F3 col = (d==0)?fb:((d==1)?fn:fc);
            ft[lane*4 + warp] = dot3(t, col);

            const int r0[15] = {0,0,0,0,0,1,1,1,1,2,2,2,3,3,4};
            const int r1[15] = {1,2,3,4,5,2,3,4,5,3,4,5,4,5,5};
            F3 P[6] = {A0,A1,A2,A3,A4,A5};
            F3 dd = f3sub(P[r0[lane]], P[r1[lane]]);
            float Dn = sqrtf(dot3(dd,dd));
            #pragma unroll
            for (int q = 0; q < RBFN; q++){
                float t2 = (Dn - (float)q*(20.0f/15.0f)) * 0.8f;
                ft[(27 + lane*RBFN + q)*4 + warp] = __expf(-t2*t2);
            }
        } else if (lane < 18){
            int s = lane - 15;
            int p = 3*l + s;
            float Dd = 0.f, Db = 0.f;
            if (p >= 1 && p <= 3*Lc - 3){
                int raw = p - 1;
                F3 P0 = ldP(xyz,b,raw),   P1 = ldP(xyz,b,raw+1);
                F3 P2 = ldP(xyz,b,raw+2), P3 = ldP(xyz,b,raw+3);
                F3 u2 = norm3v(f3sub(P1,P0));
                F3 u1 = norm3v(f3sub(P2,P1));
                F3 u0 = norm3v(f3sub(P3,P2));
                F3 n2 = norm3v(cross3(u2,u1));
                F3 n1 = norm3v(cross3(u1,u0));
                float cd = fminf(fmaxf(dot3(n2,n1), -1.f + 1e-7f), 1.f - 1e-7f);
                Dd = sgnf(dot3(u2,n1)) * acosf(cd);
                float cb = fminf(fmaxf(dot3(u2,u1), -1.f + 1e-7f), 1.f - 1e-7f);
                Db = acosf(cb);
            }
            float cDd = cosf(Dd), sDd = sinf(Dd), cDb = cosf(Db), sDb = sinf(Db);
            if (l == g_last[b]){ cDd = 0.f; sDd = 0.f; cDb = 0.f; sDb = 0.f; }
            ft[(15 + s)*4 + warp] = cDd;
            ft[(18 + s)*4 + warp] = sDd;
            ft[(21 + s)*4 + warp] = cDb;
            ft[(24 + s)*4 + warp] = sDb;
        }
    }
    __syncthreads();

    int h = tid;
    float bias = nb[h];
    unsigned long long acc0 = pack2(bias, bias);
    unsigned long long acc1 = pack2(bias, bias);
    const ulonglong2* ftu = reinterpret_cast<const ulonglong2*>(ft);
    for (int f = 0; f < NFN; f++){
        float wf = __ldg(nw + f*Hc + h);
        unsigned long long w2 = pack2(wf, wf);
        ulonglong2 a = ftu[f];
        pfma(acc0, a.x, w2);
        pfma(acc1, a.y, w2);
    }
    float y0,y1,y2,y3;
    unpack2(acc0, y0, y1);
    unpack2(acc1, y2, y3);
    outs[0][h] = y0; outs[1][h] = y1; outs[2][h] = y2; outs[3][h] = y3;
    __syncthreads();

    if (tid < 4){
        float s = 0.f;
        for (int q = 0; q < Hc; q++) s += outs[tid][q];
        float mu = s / (float)Hc;
        float s2 = 0.f;
        for (int q = 0; q < Hc; q++){ float d = outs[tid][q] - mu; s2 += d*d; }
        smu[tid] = mu;
        srs[tid] = 1.f / sqrtf(s2 / (float)Hc + 1e-5f);
    }
    __syncthreads();

    int row0 = blockIdx.x*4;
    float gh = lg[h], bh = lb[h];
    #pragma unroll
    for (int r = 0; r < 4; r++){
        out[(size_t)(row0 + r)*Hc + h] = (outs[r][h] - smu[r])*srs[r]*gh + bh;
    }
}

// ---------------------------------------------------------------------------
// Edge via mma.sync bf16 3-pass split (exact R8 WIN version: 162 regs, 3 CTAs).
// ---------------------------------------------------------------------------
#define A_STRIDE 136                 // bf16 elems per row (272 bytes)
#define A_BYTES  (64*A_STRIDE*2)     // 17408 per array

__device__ __forceinline__ void edge_wAB(unsigned short* Ah, unsigned short* Al, int idx, float v){
    __nv_bfloat16 h = __float2bfloat16(v);
    Ah[idx] = *reinterpret_cast<unsigned short*>(&h);
    __nv_bfloat16 lo = __float2bfloat16(v - __bfloat162float(h));
    Al[idx] = *reinterpret_cast<unsigned short*>(&lo);
}

__global__ void __launch_bounds__(128) edge_kernel(const float* __restrict__ xyz,
                            const float* __restrict__ eb,
                            const float* __restrict__ lg, const float* __restrict__ lb,
                            float* __restrict__ out){
    __shared__ __align__(16) unsigned char sA[2*A_BYTES];   // Ahi | Alo ; aliased by LN staging
    __shared__ float seb[Hc];
    __shared__ float smu[64], srs[64];

    int tid = threadIdx.x;
    int warp = tid >> 5, lane = tid & 31;
    int b = blockIdx.y;
    int l0 = blockIdx.x*2;
    int base0 = b*Lc + l0;

    unsigned short* Ah = reinterpret_cast<unsigned short*>(sA);
    unsigned short* Al = reinterpret_cast<unsigned short*>(sA + A_BYTES);

    {
        uint4* p = reinterpret_cast<uint4*>(sA);
        #pragma unroll
        for (int i = tid; i < (2*A_BYTES)/16; i += 128) p[i] = make_uint4(0,0,0,0);
    }
    if (tid < Hc) seb[tid] = eb[tid];
    __syncthreads();

    if (tid < 120){
        int r = tid >> 1, sub = tid & 1;
        int res = r / 30;
        int base = base0 + res;
        int j = g_eidx[(size_t)base*Kc + (r - 30*res)];
        const float* api = xyz + (size_t)base*18;
        const float* apj = xyz + (size_t)(b*Lc + j)*18;
        F3 Ca = ld3(api + 3);

        F3 Ai0 = ld3(api+0), Ai2 = ld3(api+6);
        F3 u = norm3v(f3sub(Ai0, Ca));
        F3 v = norm3v(f3sub(Ca, Ai2));
        F3 fb = norm3v(f3sub(u,v));
        F3 fn = norm3v(cross3(u,v));
        F3 fc = cross3(fb,fn);

        int ro = r*A_STRIDE;
        if (sub == 0){
            #pragma unroll
            for (int a = 0; a < 3; a++){
                F3 tv = norm3v(f3sub(ld3(apj + a*3), Ca));
                edge_wAB(Ah, Al, ro + a*3+0, dot3(tv, fb));
                edge_wAB(Ah, Al, ro + a*3+1, dot3(tv, fn));
                edge_wAB(Ah, Al, ro + a*3+2, dot3(tv, fc));
            }
            #pragma unroll
            for (int a = 0; a < 3; a++){
                F3 d = f3sub(ld3(apj + a*3), Ca);
                float De = sqrtf(dot3(d,d));
                #pragma unroll
                for (int q = 0; q < RBFN; q++){
                    float t2 = (De - (float)q*(20.0f/15.0f))*0.8f;
                    edge_wAB(Ah, Al, ro + 25 + a*RBFN + q, __expf(-t2*t2));
                }
            }
        } else {
            #pragma unroll
            for (int a = 3; a < 6; a++){
                F3 tv = norm3v(f3sub(ld3(apj + a*3), Ca));
                edge_wAB(Ah, Al, ro + a*3+0, dot3(tv, fb));
                edge_wAB(Ah, Al, ro + a*3+1, dot3(tv, fn));
                edge_wAB(Ah, Al, ro + a*3+2, dot3(tv, fc));
            }
            float Om[9], On[9];
            #pragma unroll
            for (int q = 0; q < 9; q++) Om[q] = g_O[(size_t)base*9 + q];
            #pragma unroll
            for (int q = 0; q < 9; q++) On[q] = g_O[(size_t)(b*Lc + j)*9 + q];
            F3 Cj = ld3(apj + 3);
            F3 dX = f3sub(Cj, Ca);
            float d0 = Om[0]*dX.x + Om[1]*dX.y + Om[2]*dX.z;
            float d1 = Om[3]*dX.x + Om[4]*dX.y + Om[5]*dX.z;
            float d2 = Om[6]*dX.x + Om[7]*dX.y + Om[8]*dX.z;
            float nn = sqrtf(d0*d0 + d1*d1 + d2*d2);
            float inv = 1.f / fmaxf(nn, 1e-12f);
            edge_wAB(Ah, Al, ro + 18, d0*inv);
            edge_wAB(Ah, Al, ro + 19, d1*inv);
            edge_wAB(Ah, Al, ro + 20, d2*inv);
            float R[3][3];
            #pragma unroll
            for (int ii = 0; ii < 3; ii++)
                #pragma unroll
                for (int m = 0; m < 3; m++)
                    R[ii][m] = Om[0*3+ii]*On[0*3+m] + Om[1*3+ii]*On[1*3+m] + Om[2*3+ii]*On[2*3+m];
            float Rxx = R[0][0], Ryy = R[1][1], Rzz = R[2][2];
            float mx = 0.5f*sqrtf(fabsf(1.f + Rxx - Ryy - Rzz));
            float my = 0.5f*sqrtf(fabsf(1.f - Rxx + Ryy - Rzz));
            float mz = 0.5f*sqrtf(fabsf(1.f - Rxx - Ryy + Rzz));
            float qx = sgnf(R[2][1] - R[1][2]) * mx;
            float qy = sgnf(R[0][2] - R[2][0]) * my;
            float qz = sgnf(R[1][0] - R[0][1]) * mz;
            float qw = sqrtf(fmaxf(1.f + Rxx + Ryy + Rzz, 0.f)) * 0.5f;
            float qn = sqrtf(qx*qx + qy*qy + qz*qz + qw*qw);
            float qi = 1.f / fmaxf(qn, 1e-12f);
            edge_wAB(Ah, Al, ro + 21, qx*qi);
            edge_wAB(Ah, Al, ro + 22, qy*qi);
            edge_wAB(Ah, Al, ro + 23, qz*qi);
            edge_wAB(Ah, Al, ro + 24, qw*qi);
            #pragma unroll
            for (int a = 3; a < 6; a++){
                F3 d = f3sub(ld3(apj + a*3), Ca);
                float De = sqrtf(dot3(d,d));
                #pragma unroll
                for (int q = 0; q < RBFN; q++){
                    float t2 = (De - (float)q*(20.0f/15.0f))*0.8f;
                    edge_wAB(Ah, Al, ro + 25 + a*RBFN + q, __expf(-t2*t2));
                }
            }
        }
    }
    __syncthreads();

    float acc[4][4][4];
    #pragma unroll
    for (int mt = 0; mt < 4; mt++)
        #pragma unroll
        for (int nt = 0; nt < 4; nt++)
            #pragma unroll
            for (int q = 0; q < 4; q++) acc[mt][nt][q] = 0.f;

    unsigned aHiB = smem_u32(Ah);
    unsigned aLoB = smem_u32(Al);
    unsigned rowterm = (lane & 7) + ((lane >> 3) & 1)*8;
    unsigned colterm = ((lane >> 4) & 1)*16;   // bytes

    #pragma unroll
    for (int kt = 0; kt < 8; kt++){
        uint2 bh[4], bl[4];
        #pragma unroll
        for (int nt = 0; nt < 4; nt++){
            int idx = (kt*16 + warp*4 + nt)*32 + lane;
            bh[nt] = __ldg(g_Wh + idx);
            bl[nt] = __ldg(g_Wl + idx);
        }
        #pragma unroll
        for (int mt = 0; mt < 4; mt++){
            unsigned off = (mt*16 + rowterm)*(A_STRIDE*2) + (unsigned)kt*32 + colterm;
            unsigned ah[4], al[4];
            ldm4(ah, aHiB + off);
            ldm4(al, aLoB + off);
            #pragma unroll
            for (int nt = 0; nt < 4; nt++){
                mma_bf16(acc[mt][nt], ah[0], ah[1], ah[2], ah[3], bh[nt].x, bh[nt].y);
                mma_bf16(acc[mt][nt], ah[0], ah[1], ah[2], ah[3], bl[nt].x, bl[nt].y);
                mma_bf16(acc[mt][nt], al[0], al[1], al[2], al[3], bh[nt].x, bh[nt].y);
            }
        }
    }
    __syncthreads();

    float* lnb = reinterpret_cast<float*>(sA);   // [64][130]
    int g = lane >> 2, tg = lane & 3;
    #pragma unroll
    for (int mt = 0; mt < 4; mt++){
        #pragma unroll
        for (int nt = 0; nt < 4; nt++){
            int row = mt*16 + g;
            int col = (warp*4 + nt)*8 + 2*tg;
            float e0 = seb[col], e1 = seb[col+1];
            *reinterpret_cast<unsigned long long*>(lnb + row*130 + col) =
                pack2(acc[mt][nt][0] + e0, acc[mt][nt][1] + e1);
            *reinterpret_cast<unsigned long long*>(lnb + (row+8)*130 + col) =
                pack2(acc[mt][nt][2] + e0, acc[mt][nt][3] + e1);
        }
    }
    __syncthreads();

    if (tid < 60){
        float s = 0.f;
        for (int q = 0; q < Hc; q++) s += lnb[tid*130 + q];
        float mu = s / (float)Hc;
        float s2 = 0.f;
        for (int q = 0; q < Hc; q++){ float d = lnb[tid*130 + q] - mu; s2 += d*d; }
        smu[tid] = mu;
        srs[tid] = 1.f / sqrtf(s2 / (float)Hc + 1e-5f);
    }
    __syncthreads();

    int G = tid >> 6, c = tid & 63;
    int h0 = 2*c, h1 = h0 + 1;
    float g0 = lg[h0], bb0 = lb[h0];
    float g1 = lg[h1], bb1 = lb[h1];
    size_t obase = ((size_t)(base0 + G)*Kc)*Hc;
    #pragma unroll 5
    for (int rr = 0; rr < Kc; rr++){
        int r = G*30 + rr;
        float mu = smu[r], rs = srs[r];
        float2 y = *reinterpret_cast<const float2*>(lnb + r*130 + h0);
        float2 o2;
        o2.x = (y.x - mu)*rs*g0 + bb0;
        o2.y = (y.y - mu)*rs*g1 + bb1;
        *reinterpret_cast<float2*>(out + obase + (size_t)rr*Hc + h0) = o2;
    }
}

// ---------------------------------------------------------------------------
// Launch with graph-capturable stream fork:
//   stream0: prep -> node          side s1: knn -> edge(waits prep too)
// ---------------------------------------------------------------------------
extern "C" void kernel_launch(void* const* d_in, const int* in_sizes, int n_in,
                              void* d_out, int out_size){
    const float* xyz    = (const float*)d_in[0];
    const float* mask   = (const float*)d_in[1];
    const float* node_w = (const float*)d_in[2];
    const float* node_b = (const float*)d_in[3];
    const float* edge_w = (const float*)d_in[4];
    const float* edge_b = (const float*)d_in[5];
    const float* ln_ng  = (const float*)d_in[6];
    const float* ln_nb  = (const float*)d_in[7];
    const float* ln_eg  = (const float*)d_in[8];
    const float* ln_eb  = (const float*)d_in[9];

    float* out = (float*)d_out;
    float* out_node = out;
    float* out_edge = out + (size_t)Bc*Lc*Hc;
    float* out_eidx = out_edge + (size_t)Bc*Lc*Kc*Hc;

    static cudaStream_t s1 = nullptr;
    static cudaEvent_t evFork = nullptr, evPrep = nullptr, evJoin = nullptr;
    if (s1 == nullptr){
        cudaStreamCreateWithFlags(&s1, cudaStreamNonBlocking);
        cudaEventCreateWithFlags(&evFork, cudaEventDisableTiming);
        cudaEventCreateWithFlags(&evPrep, cudaEventDisableTiming);
        cudaEventCreateWithFlags(&evJoin, cudaEventDisableTiming);
    }

    const int knn_smem = (4*Lc + QPB*Lc) * (int)sizeof(float); // 96 KB
    cudaFuncSetAttribute(knn_kernel, cudaFuncAttributeMaxDynamicSharedMemorySize, knn_smem);

    // fork: knn runs on s1 concurrently with prep on stream 0
    cudaEventRecord(evFork, 0);
    cudaStreamWaitEvent(s1, evFork, 0);

    knn_kernel<<<dim3(Lc/QPB, Bc), 256, knn_smem, s1>>>(xyz, mask, out_eidx);
    prep_kernel<<<(Bc*Lc + 255)/256, 256>>>(xyz, mask, edge_w);
    cudaEventRecord(evPrep, 0);

    // node on stream 0 (needs prep only)
    node_kernel<<<(Bc*Lc)/4, 128>>>(xyz, node_w, node_b, ln_ng, ln_nb, out_node);

    // edge on s1 (needs knn [same stream] + prep [event])
    cudaStreamWaitEvent(s1, evPrep, 0);
    edge_kernel<<<dim3(Lc/2, Bc), 128, 0, s1>>>(xyz, edge_b, ln_eg, ln_eb, out_edge);

    // join back to stream 0
    cudaEventRecord(evJoin, s1);
    cudaStreamWaitEvent(0, evJoin, 0);
}

// round 16
// speedup vs baseline: 1.2985x; 1.0149x over previous
#include <cuda_runtime.h>
#include <cuda_bf16.h>

// Problem constants
#define Bc 2
#define Lc 2048
#define Kc 30
#define Hc 128
#define RBFN 16
#define NFN 267   // node features
#define NFE 121   // edge features
#define QPB 8     // knn queries per block (one per warp)

// Scratch (device globals: allocation-free rule)
__device__ int   g_eidx[Bc*Lc*Kc];
__device__ float g_O[Bc*Lc*9];
__device__ int   g_last[Bc];
// Edge weights prepacked as per-lane mma fragments: [kt(8)][ntg(16)][lane(32)] uint2
__device__ uint2 g_Wh[4096];
__device__ uint2 g_Wl[4096];

struct F3 { float x, y, z; };
__device__ __forceinline__ F3 f3sub(F3 a, F3 b){ return {a.x-b.x, a.y-b.y, a.z-b.z}; }
__device__ __forceinline__ float dot3(F3 a, F3 b){ return a.x*b.x + a.y*b.y + a.z*b.z; }
__device__ __forceinline__ F3 cross3(F3 a, F3 b){
    return { a.y*b.z - a.z*b.y, a.z*b.x - a.x*b.z, a.x*b.y - a.y*b.x };
}
__device__ __forceinline__ F3 norm3v(F3 a){
    float n = sqrtf(dot3(a,a));
    float d = fmaxf(n, 1e-12f);
    return { a.x/d, a.y/d, a.z/d };
}
__device__ __forceinline__ F3 ld3(const float* p){ return { p[0], p[1], p[2] }; }
__device__ __forceinline__ float sgnf(float x){ return (x > 0.f) ? 1.f : ((x < 0.f) ? -1.f : 0.f); }

// packed f32x2 helpers (node kernel)
__device__ __forceinline__ unsigned long long pack2(float a, float b){
    unsigned long long r;
    asm("mov.b64 %0, {%1, %2};" : "=l"(r) : "f"(a), "f"(b));
    return r;
}
__device__ __forceinline__ void unpack2(unsigned long long v, float& a, float& b){
    asm("mov.b64 {%0, %1}, %2;" : "=f"(a), "=f"(b) : "l"(v));
}
__device__ __forceinline__ void pfma(unsigned long long& acc, unsigned long long a, unsigned long long b){
    asm("fma.rn.f32x2 %0, %1, %2, %0;" : "+l"(acc) : "l"(a), "l"(b));
}

__device__ __forceinline__ unsigned smem_u32(const void* p){
    unsigned a;
    asm("{ .reg .u64 t; cvta.to.shared.u64 t, %1; cvt.u32.u64 %0, t; }" : "=r"(a) : "l"(p));
    return a;
}
__device__ __forceinline__ unsigned pack_bf2(float a, float b){
    __nv_bfloat162 t = __floats2bfloat162_rn(a, b);
    return *reinterpret_cast<unsigned*>(&t);
}
__device__ __forceinline__ void mma_bf16(float* d, unsigned a0, unsigned a1, unsigned a2, unsigned a3,
                                         unsigned b0, unsigned b1){
    asm volatile("mma.sync.aligned.m16n8k16.row.col.f32.bf16.bf16.f32 "
        "{%0,%1,%2,%3}, {%4,%5,%6,%7}, {%8,%9}, {%0,%1,%2,%3};"
        : "+f"(d[0]), "+f"(d[1]), "+f"(d[2]), "+f"(d[3])
        : "r"(a0), "r"(a1), "r"(a2), "r"(a3), "r"(b0), "r"(b1));
}
__device__ __forceinline__ void ldm4(unsigned* a, unsigned addr){
    asm volatile("ldmatrix.sync.aligned.m8n8.x4.shared.b16 {%0,%1,%2,%3}, [%4];"
        : "=r"(a[0]), "=r"(a[1]), "=r"(a[2]), "=r"(a[3]) : "r"(addr));
}

// xyz layout: [B][L][6][3] row-major
__device__ __forceinline__ const float* atom_ptr(const float* xyz, int b, int l, int a){
    return xyz + (((size_t)(b*Lc + l))*6 + a)*3;
}
__device__ __forceinline__ F3 ldP(const float* xyz, int b, int t){
    int r = t / 3, a = t - 3*r;
    return ld3(atom_ptr(xyz, b, r, a));
}

// ---------------------------------------------------------------------------
// prep: frames O + last index + edge-weight bf16 hi/lo fragment prepack
// ---------------------------------------------------------------------------
__global__ void prep_kernel(const float* __restrict__ xyz, const float* __restrict__ mask,
                            const float* __restrict__ ew){
    int gid = blockIdx.x*blockDim.x + threadIdx.x;
    if (blockIdx.x == 0 && threadIdx.x < 64){
        int b = threadIdx.x >> 5, lane = threadIdx.x & 31;
        float s = 0.f;
        for (int m = lane; m < Lc; m += 32) s += mask[b*Lc + m];
        #pragma unroll
        for (int o = 16; o; o >>= 1) s += __shfl_xor_sync(0xffffffffu, s, o);
        if (lane == 0) g_last[b] = (int)s - 1;
    }
    if (gid < Bc*Lc){
        int b = gid / Lc, l = gid % Lc;
        float o[9] = {0,0,0,0,0,0,0,0,0};
        if (l >= 1 && l <= Lc-3){
            F3 cm = ld3(atom_ptr(xyz,b,l-1,1));
            F3 c0 = ld3(atom_ptr(xyz,b,l  ,1));
            F3 cp = ld3(atom_ptr(xyz,b,l+1,1));
            F3 u2 = norm3v(f3sub(c0,cm));
            F3 u1 = norm3v(f3sub(cp,c0));
            F3 o1 = norm3v(f3sub(u2,u1));
            F3 n2 = norm3v(cross3(u2,u1));
            F3 o3 = cross3(o1,n2);
            o[0]=o1.x; o[1]=o1.y; o[2]=o1.z;
            o[3]=n2.x; o[4]=n2.y; o[5]=n2.z;
            o[6]=o3.x; o[7]=o3.y; o[8]=o3.z;
        }
        #pragma unroll
        for (int q = 0; q < 9; q++) g_O[(size_t)gid*9 + q] = o[q];
    }
    // W fragment prepack: gid = kt*512 + ntg*32 + lane
    if (gid < 4096){
        int lane = gid & 31;
        int ntg  = (gid >> 5) & 15;
        int kt   = gid >> 9;
        int g = lane >> 2, tg = lane & 3;
        int n = ntg*8 + g;
        int k0 = kt*16 + 2*tg;
        float w00 = (k0   < NFE) ? ew[(k0  )*Hc + n] : 0.f;
        float w01 = (k0+1 < NFE) ? ew[(k0+1)*Hc + n] : 0.f;
        float w10 = (k0+8 < NFE) ? ew[(k0+8)*Hc + n] : 0.f;
        float w11 = (k0+9 < NFE) ? ew[(k0+9)*Hc + n] : 0.f;
        float h00 = __bfloat162float(__float2bfloat16(w00));
        float h01 = __bfloat162float(__float2bfloat16(w01));
        float h10 = __bfloat162float(__float2bfloat16(w10));
        float h11 = __bfloat162float(__float2bfloat16(w11));
        g_Wh[gid] = make_uint2(pack_bf2(h00, h01), pack_bf2(h10, h11));
        g_Wl[gid] = make_uint2(pack_bf2(w00-h00, w01-h01), pack_bf2(w10-h10, w11-h11));
    }
}

// ---------------------------------------------------------------------------
// KNN: one warp per query, stored per-warp distance row, SoA coords (R13).
// Processes a single batch (bofs); grid y = 1.
// ---------------------------------------------------------------------------
__device__ __forceinline__ void knn_insert3(float d, int j,
    float& v1, int& i1, float& v2, int& i2, float& v3, int& i3){
    if (d < v3){
        if (d < v2){
            if (d < v1){ v3=v2; i3=i2; v2=v1; i2=i1; v1=d; i1=j; }
            else       { v3=v2; i3=i2; v2=d;  i2=j; }
        } else         { v3=d;  i3=j; }
    }
}

__global__ void __launch_bounds__(256) knn_kernel(const float* __restrict__ xyz,
                                                  const float* __restrict__ mask,
                                                  float* __restrict__ out_eidx,
                                                  int bofs){
    extern __shared__ float dyns[];
    float* sx  = dyns;              // Lc
    float* sy  = sx + Lc;           // Lc
    float* sz  = sy + Lc;           // Lc
    float* smk = sz + Lc;           // Lc
    float* sdall = smk + Lc;        // QPB*Lc

    int tid = threadIdx.x;
    int w = tid >> 5, lane = tid & 31;
    int b = bofs;
    int i = blockIdx.x*QPB + w;

    for (int j = tid; j < Lc; j += 256){
        const float* p = atom_ptr(xyz, b, j, 1);
        sx[j] = p[0]; sy[j] = p[1]; sz[j] = p[2];
        smk[j] = mask[b*Lc + j];
    }
    __syncthreads();

    float* sdr = sdall + w*Lc;
    float xi = sx[i], yi = sy[i], zi = sz[i];
    float mi = smk[i];

    float dmax = -1e30f;
    #pragma unroll 4
    for (int m = 0; m < 64; m++){
        int j = lane + 32*m;
        float dx = __fadd_rn(sx[j], -xi);
        float dy = __fadd_rn(sy[j], -yi);
        float dz = __fadd_rn(sz[j], -zi);
        float s  = __fadd_rn(__fadd_rn(__fmul_rn(dx,dx), __fmul_rn(dy,dy)), __fmul_rn(dz,dz));
        float D  = __fmul_rn(__fmul_rn(smk[j], mi), __fsqrt_rn(__fadd_rn(s, 1e-6f)));
        sdr[j] = D;
        dmax = fmaxf(dmax, D);
    }
    {
        unsigned mb = __reduce_max_sync(0xffffffffu, __float_as_uint(dmax));
        dmax = __uint_as_float(mb);
    }

    float v1 = 1e38f, v2 = 1e38f, v3 = 1e38f;
    int   i1 = 0x7fffffff, i2 = 0x7fffffff, i3 = 0x7fffffff;
    #pragma unroll 4
    for (int m = 0; m < 64; m++){
        int j = lane + 32*m;
        float m2 = __fmul_rn(smk[j], mi);
        float d = __fadd_rn(sdr[j], __fmul_rn(__fadd_rn(1.0f, -m2), dmax));
        sdr[j] = d;
        knn_insert3(d, j, v1, i1, v2, i2, v3, i3);
    }

    size_t obase = (size_t)(b*Lc + i)*Kc;
    for (int it = 0; it < Kc; it++){
        unsigned myb = __float_as_uint(v1);
        unsigned kb = __reduce_min_sync(0xffffffffu, myb);
        unsigned cand = (myb == kb) ? (unsigned)i1 : 0xffffffffu;
        unsigned ib = __reduce_min_sync(0xffffffffu, cand);
        if (lane == 0){
            g_eidx[obase + it] = (int)ib;
            out_eidx[obase + it] = (float)ib;
        }
        if (myb == kb && (unsigned)i1 == ib){
            sdr[i1] = 1e38f;
            v1 = v2; i1 = i2;
            v2 = v3; i2 = i3;
            v3 = 1e38f; i3 = 0x7fffffff;
            if (v1 == 1e38f && it < Kc-1){
                v1 = v2 = v3 = 1e38f; i1 = i2 = i3 = 0x7fffffff;
                #pragma unroll 8
                for (int m = 0; m < 64; m++){
                    int j = lane + 32*m;
                    float d = sdr[j];
                    knn_insert3(d, j, v1, i1, v2, i2, v3, i3);
                }
            }
        }
    }
}

// ---------------------------------------------------------------------------
// Node (exact R8 version — warp-coalesced scalar weight loads)
// ---------------------------------------------------------------------------
__global__ void __launch_bounds__(128) node_kernel(const float* __restrict__ xyz,
                            const float* __restrict__ nw, const float* __restrict__ nb,
                            const float* __restrict__ lg, const float* __restrict__ lb,
                            float* __restrict__ out){
    __shared__ __align__(16) float ft[NFN*4];
    __shared__ float outs[4][Hc+1];
    __shared__ float smu[4], srs[4];

    int tid = threadIdx.x;
    int warp = tid >> 5, lane = tid & 31;
    int gid = blockIdx.x*4 + warp;
    int b = gid / Lc, l = gid % Lc;

    {
        const float* ap = xyz + (size_t)gid*18;
        F3 A0 = ld3(ap+0), A1 = ld3(ap+3), A2 = ld3(ap+6);
        F3 A3 = ld3(ap+9), A4 = ld3(ap+12), A5 = ld3(ap+15);
        F3 u = norm3v(f3sub(A0,A1));
        F3 v = norm3v(f3sub(A1,A2));
        F3 fb = norm3v(f3sub(u,v));
        F3 fn = norm3v(cross3(u,v));
        F3 fc = cross3(fb,fn);

        if (lane < 15){
            const int sel[5] = {0,2,3,4,5};
            int a = lane/3, d = lane%3;
            F3 Aa = (sel[a]==0)?A0:((sel[a]==2)?A2:((sel[a]==3)?A3:((sel[a]==4)?A4:A5)));
            F3 t = norm3v(f3sub(Aa, A1));
            F3 col = (d==0)?fb:((d==1)?fn:fc);
            ft[lane*4 + warp] = dot3(t, col);

            const int r0[15] = {0,0,0,0,0,1,1,1,1,2,2,2,3,3,4};
            const int r1[15] = {1,2,3,4,5,2,3,4,5,3,4,5,4,5,5};
            F3 P[6] = {A0,A1,A2,A3,A4,A5};
            F3 dd = f3sub(P[r0[lane]], P[r1[lane]]);
            float Dn = sqrtf(dot3(dd,dd));
            #pragma unroll
            for (int q = 0; q < RBFN; q++){
                float t2 = (Dn - (float)q*(20.0f/15.0f)) * 0.8f;
                ft[(27 + lane*RBFN + q)*4 + warp] = __expf(-t2*t2);
            }
        } else if (lane < 18){
            int s = lane - 15;
            int p = 3*l + s;
            float Dd = 0.f, Db = 0.f;
            if (p >= 1 && p <= 3*Lc - 3){
                int raw = p - 1;
                F3 P0 = ldP(xyz,b,raw),   P1 = ldP(xyz,b,raw+1);
                F3 P2 = ldP(xyz,b,raw+2), P3 = ldP(xyz,b,raw+3);
                F3 u2 = norm3v(f3sub(P1,P0));
                F3 u1 = norm3v(f3sub(P2,P1));
                F3 u0 = norm3v(f3sub(P3,P2));
                F3 n2 = norm3v(cross3(u2,u1));
                F3 n1 = norm3v(cross3(u1,u0));
                float cd = fminf(fmaxf(dot3(n2,n1), -1.f + 1e-7f), 1.f - 1e-7f);
                Dd = sgnf(dot3(u2,n1)) * acosf(cd);
                float cb = fminf(fmaxf(dot3(u2,u1), -1.f + 1e-7f), 1.f - 1e-7f);
                Db = acosf(cb);
            }
            float cDd = cosf(Dd), sDd = sinf(Dd), cDb = cosf(Db), sDb = sinf(Db);
            if (l == g_last[b]){ cDd = 0.f; sDd = 0.f; cDb = 0.f; sDb = 0.f; }
            ft[(15 + s)*4 + warp] = cDd;
            ft[(18 + s)*4 + warp] = sDd;
            ft[(21 + s)*4 + warp] = cDb;
            ft[(24 + s)*4 + warp] = sDb;
        }
    }
    __syncthreads();

    int h = tid;
    float bias = nb[h];
    unsigned long long acc0 = pack2(bias, bias);
    unsigned long long acc1 = pack2(bias, bias);
    const ulonglong2* ftu = reinterpret_cast<const ulonglong2*>(ft);
    for (int f = 0; f < NFN; f++){
        float wf = __ldg(nw + f*Hc + h);
        unsigned long long w2 = pack2(wf, wf);
        ulonglong2 a = ftu[f];
        pfma(acc0, a.x, w2);
        pfma(acc1, a.y, w2);
    }
    float y0,y1,y2,y3;
    unpack2(acc0, y0, y1);
    unpack2(acc1, y2, y3);
    outs[0][h] = y0; outs[1][h] = y1; outs[2][h] = y2; outs[3][h] = y3;
    __syncthreads();

    if (tid < 4){
        float s = 0.f;
        for (int q = 0; q < Hc; q++) s += outs[tid][q];
        float mu = s / (float)Hc;
        float s2 = 0.f;
        for (int q = 0; q < Hc; q++){ float d = outs[tid][q] - mu; s2 += d*d; }
        smu[tid] = mu;
        srs[tid] = 1.f / sqrtf(s2 / (float)Hc + 1e-5f);
    }
    __syncthreads();

    int row0 = blockIdx.x*4;
    float gh = lg[h], bh = lb[h];
    #pragma unroll
    for (int r = 0; r < 4; r++){
        out[(size_t)(row0 + r)*Hc + h] = (outs[r][h] - smu[r])*srs[r]*gh + bh;
    }
}

// ---------------------------------------------------------------------------
// Edge via mma.sync bf16 3-pass split (exact R8 WIN version: 162 regs, 3 CTAs).
// Processes a single batch (bofs); grid y = 1.
// ---------------------------------------------------------------------------
#define A_STRIDE 136                 // bf16 elems per row (272 bytes)
#define A_BYTES  (64*A_STRIDE*2)     // 17408 per array

__device__ __forceinline__ void edge_wAB(unsigned short* Ah, unsigned short* Al, int idx, float v){
    __nv_bfloat16 h = __float2bfloat16(v);
    Ah[idx] = *reinterpret_cast<unsigned short*>(&h);
    __nv_bfloat16 lo = __float2bfloat16(v - __bfloat162float(h));
    Al[idx] = *reinterpret_cast<unsigned short*>(&lo);
}

__global__ void __launch_bounds__(128) edge_kernel(const float* __restrict__ xyz,
                            const float* __restrict__ eb,
                            const float* __restrict__ lg, const float* __restrict__ lb,
                            float* __restrict__ out, int bofs){
    __shared__ __align__(16) unsigned char sA[2*A_BYTES];   // Ahi | Alo ; aliased by LN staging
    __shared__ float seb[Hc];
    __shared__ float smu[64], srs[64];

    int tid = threadIdx.x;
    int warp = tid >> 5, lane = tid & 31;
    int b = bofs;
    int l0 = blockIdx.x*2;
    int base0 = b*Lc + l0;

    unsigned short* Ah = reinterpret_cast<unsigned short*>(sA);
    unsigned short* Al = reinterpret_cast<unsigned short*>(sA + A_BYTES);

    {
        uint4* p = reinterpret_cast<uint4*>(sA);
        #pragma unroll
        for (int i = tid; i < (2*A_BYTES)/16; i += 128) p[i] = make_uint4(0,0,0,0);
    }
    if (tid < Hc) seb[tid] = eb[tid];
    __syncthreads();

    if (tid < 120){
        int r = tid >> 1, sub = tid & 1;
        int res = r / 30;
        int base = base0 + res;
        int j = g_eidx[(size_t)base*Kc + (r - 30*res)];
        const float* api = xyz + (size_t)base*18;
        const float* apj = xyz + (size_t)(b*Lc + j)*18;
        F3 Ca = ld3(api + 3);

        F3 Ai0 = ld3(api+0), Ai2 = ld3(api+6);
        F3 u = norm3v(f3sub(Ai0, Ca));
        F3 v = norm3v(f3sub(Ca, Ai2));
        F3 fb = norm3v(f3sub(u,v));
        F3 fn = norm3v(cross3(u,v));
        F3 fc = cross3(fb,fn);

        int ro = r*A_STRIDE;
        if (sub == 0){
            #pragma unroll
            for (int a = 0; a < 3; a++){
                F3 tv = norm3v(f3sub(ld3(apj + a*3), Ca));
                edge_wAB(Ah, Al, ro + a*3+0, dot3(tv, fb));
                edge_wAB(Ah, Al, ro + a*3+1, dot3(tv, fn));
                edge_wAB(Ah, Al, ro + a*3+2, dot3(tv, fc));
            }
            #pragma unroll
            for (int a = 0; a < 3; a++){
                F3 d = f3sub(ld3(apj + a*3), Ca);
                float De = sqrtf(dot3(d,d));
                #pragma unroll
                for (int q = 0; q < RBFN; q++){
                    float t2 = (De - (float)q*(20.0f/15.0f))*0.8f;
                    edge_wAB(Ah, Al, ro + 25 + a*RBFN + q, __expf(-t2*t2));
                }
            }
        } else {
            #pragma unroll
            for (int a = 3; a < 6; a++){
                F3 tv = norm3v(f3sub(ld3(apj + a*3), Ca));
                edge_wAB(Ah, Al, ro + a*3+0, dot3(tv, fb));
                edge_wAB(Ah, Al, ro + a*3+1, dot3(tv, fn));
                edge_wAB(Ah, Al, ro + a*3+2, dot3(tv, fc));
            }
            float Om[9], On[9];
            #pragma unroll
            for (int q = 0; q < 9; q++) Om[q] = g_O[(size_t)base*9 + q];
            #pragma unroll
            for (int q = 0; q < 9; q++) On[q] = g_O[(size_t)(b*Lc + j)*9 + q];
            F3 Cj = ld3(apj + 3);
            F3 dX = f3sub(Cj, Ca);
            float d0 = Om[0]*dX.x + Om[1]*dX.y + Om[2]*dX.z;
            float d1 = Om[3]*dX.x + Om[4]*dX.y + Om[5]*dX.z;
            float d2 = Om[6]*dX.x + Om[7]*dX.y + Om[8]*dX.z;
            float nn = sqrtf(d0*d0 + d1*d1 + d2*d2);
            float inv = 1.f / fmaxf(nn, 1e-12f);
            edge_wAB(Ah, Al, ro + 18, d0*inv);
            edge_wAB(Ah, Al, ro + 19, d1*inv);
            edge_wAB(Ah, Al, ro + 20, d2*inv);
            float R[3][3];
            #pragma unroll
            for (int ii = 0; ii < 3; ii++)
                #pragma unroll
                for (int m = 0; m < 3; m++)
                    R[ii][m] = Om[0*3+ii]*On[0*3+m] + Om[1*3+ii]*On[1*3+m] + Om[2*3+ii]*On[2*3+m];
            float Rxx = R[0][0], Ryy = R[1][1], Rzz = R[2][2];
            float mx = 0.5f*sqrtf(fabsf(1.f + Rxx - Ryy - Rzz));
            float my = 0.5f*sqrtf(fabsf(1.f - Rxx + Ryy - Rzz));
            float mz = 0.5f*sqrtf(fabsf(1.f - Rxx - Ryy + Rzz));
            float qx = sgnf(R[2][1] - R[1][2]) * mx;
            float qy = sgnf(R[0][2] - R[2][0]) * my;
            float qz = sgnf(R[1][0] - R[0][1]) * mz;
            float qw = sqrtf(fmaxf(1.f + Rxx + Ryy + Rzz, 0.f)) * 0.5f;
            float qn = sqrtf(qx*qx + qy*qy + qz*qz + qw*qw);
            float qi = 1.f / fmaxf(qn, 1e-12f);
            edge_wAB(Ah, Al, ro + 21, qx*qi);
            edge_wAB(Ah, Al, ro + 22, qy*qi);
            edge_wAB(Ah, Al, ro + 23, qz*qi);
            edge_wAB(Ah, Al, ro + 24, qw*qi);
            #pragma unroll
            for (int a = 3; a < 6; a++){
                F3 d = f3sub(ld3(apj + a*3), Ca);
                float De = sqrtf(dot3(d,d));
                #pragma unroll
                for (int q = 0; q < RBFN; q++){
                    float t2 = (De - (float)q*(20.0f/15.0f))*0.8f;
                    edge_wAB(Ah, Al, ro + 25 + a*RBFN + q, __expf(-t2*t2));
                }
            }
        }
    }
    __syncthreads();

    float acc[4][4][4];
    #pragma unroll
    for (int mt = 0; mt < 4; mt++)
        #pragma unroll
        for (int nt = 0; nt < 4; nt++)
            #pragma unroll
            for (int q = 0; q < 4; q++) acc[mt][nt][q] = 0.f;

    unsigned aHiB = smem_u32(Ah);
    unsigned aLoB = smem_u32(Al);
    unsigned rowterm = (lane & 7) + ((lane >> 3) & 1)*8;
    unsigned colterm = ((lane >> 4) & 1)*16;   // bytes

    #pragma unroll
    for (int kt = 0; kt < 8; kt++){
        uint2 bh[4], bl[4];
        #pragma unroll
        for (int nt = 0; nt < 4; nt++){
            int idx = (kt*16 + warp*4 + nt)*32 + lane;
            bh[nt] = __ldg(g_Wh + idx);
            bl[nt] = __ldg(g_Wl + idx);
        }
        #pragma unroll
        for (int mt = 0; mt < 4; mt++){
            unsigned off = (mt*16 + rowterm)*(A_STRIDE*2) + (unsigned)kt*32 + colterm;
            unsigned ah[4], al[4];
            ldm4(ah, aHiB + off);
            ldm4(al, aLoB + off);
            #pragma unroll
            for (int nt = 0; nt < 4; nt++){
                mma_bf16(acc[mt][nt], ah[0], ah[1], ah[2], ah[3], bh[nt].x, bh[nt].y);
                mma_bf16(acc[mt][nt], ah[0], ah[1], ah[2], ah[3], bl[nt].x, bl[nt].y);
                mma_bf16(acc[mt][nt], al[0], al[1], al[2], al[3], bh[nt].x, bh[nt].y);
            }
        }
    }
    __syncthreads();

    float* lnb = reinterpret_cast<float*>(sA);   // [64][130]
    int g = lane >> 2, tg = lane & 3;
    #pragma unroll
    for (int mt = 0; mt < 4; mt++){
        #pragma unroll
        for (int nt = 0; nt < 4; nt++){
            int row = mt*16 + g;
            int col = (warp*4 + nt)*8 + 2*tg;
            float e0 = seb[col], e1 = seb[col+1];
            *reinterpret_cast<unsigned long long*>(lnb + row*130 + col) =
                pack2(acc[mt][nt][0] + e0, acc[mt][nt][1] + e1);
            *reinterpret_cast<unsigned long long*>(lnb + (row+8)*130 + col) =
                pack2(acc[mt][nt][2] + e0, acc[mt][nt][3] + e1);
        }
    }
    __syncthreads();

    if (tid < 60){
        float s = 0.f;
        for (int q = 0; q < Hc; q++) s += lnb[tid*130 + q];
        float mu = s / (float)Hc;
        float s2 = 0.f;
        for (int q = 0; q < Hc; q++){ float d = lnb[tid*130 + q] - mu; s2 += d*d; }
        smu[tid] = mu;
        srs[tid] = 1.f / sqrtf(s2 / (float)Hc + 1e-5f);
    }
    __syncthreads();

    int G = tid >> 6, c = tid & 63;
    int h0 = 2*c, h1 = h0 + 1;
    float g0 = lg[h0], bb0 = lb[h0];
    float g1 = lg[h1], bb1 = lb[h1];
    size_t obase = ((size_t)(base0 + G)*Kc)*Hc;
    #pragma unroll 5
    for (int rr = 0; rr < Kc; rr++){
        int r = G*30 + rr;
        float mu = smu[r], rs = srs[r];
        float2 y = *reinterpret_cast<const float2*>(lnb + r*130 + h0);
        float2 o2;
        o2.x = (y.x - mu)*rs*g0 + bb0;
        o2.y = (y.y - mu)*rs*g1 + bb1;
        *reinterpret_cast<float2*>(out + obase + (size_t)rr*Hc + h0) = o2;
    }
}

// ---------------------------------------------------------------------------
// Launch with batch-pipelined stream fork:
//   s0: prep -> node
//   s1: knn(b0) -> knn(b1) -> edge(b1)   [edge waits prep via event]
//   s2: [waits knn(b0), prep] edge(b0)
// ---------------------------------------------------------------------------
extern "C" void kernel_launch(void* const* d_in, const int* in_sizes, int n_in,
                              void* d_out, int out_size){
    const float* xyz    = (const float*)d_in[0];
    const float* mask   = (const float*)d_in[1];
    const float* node_w = (const float*)d_in[2];
    const float* node_b = (const float*)d_in[3];
    const float* edge_w = (const float*)d_in[4];
    const float* edge_b = (const float*)d_in[5];
    const float* ln_ng  = (const float*)d_in[6];
    const float* ln_nb  = (const float*)d_in[7];
    const float* ln_eg  = (const float*)d_in[8];
    const float* ln_eb  = (const float*)d_in[9];

    float* out = (float*)d_out;
    float* out_node = out;
    float* out_edge = out + (size_t)Bc*Lc*Hc;
    float* out_eidx = out_edge + (size_t)Bc*Lc*Kc*Hc;

    static cudaStream_t s1 = nullptr, s2 = nullptr;
    static cudaEvent_t evFork = nullptr, evPrep = nullptr, evK0 = nullptr;
    static cudaEvent_t evJoin1 = nullptr, evJoin2 = nullptr;
    if (s1 == nullptr){
        cudaStreamCreateWithFlags(&s1, cudaStreamNonBlocking);
        cudaStreamCreateWithFlags(&s2, cudaStreamNonBlocking);
        cudaEventCreateWithFlags(&evFork, cudaEventDisableTiming);
        cudaEventCreateWithFlags(&evPrep, cudaEventDisableTiming);
        cudaEventCreateWithFlags(&evK0,   cudaEventDisableTiming);
        cudaEventCreateWithFlags(&evJoin1, cudaEventDisableTiming);
        cudaEventCreateWithFlags(&evJoin2, cudaEventDisableTiming);
    }

    const int knn_smem = (4*Lc + QPB*Lc) * (int)sizeof(float); // 96 KB
    cudaFuncSetAttribute(knn_kernel, cudaFuncAttributeMaxDynamicSharedMemorySize, knn_smem);

    // fork
    cudaEventRecord(evFork, 0);
    cudaStreamWaitEvent(s1, evFork, 0);

    // s1: knn b0, then knn b1
    knn_kernel<<<dim3(Lc/QPB, 1), 256, knn_smem, s1>>>(xyz, mask, out_eidx, 0);
    cudaEventRecord(evK0, s1);
    knn_kernel<<<dim3(Lc/QPB, 1), 256, knn_smem, s1>>>(xyz, mask, out_eidx, 1);

    // s0: prep, then node
    prep_kernel<<<(Bc*Lc + 255)/256, 256>>>(xyz, mask, edge_w);
    cudaEventRecord(evPrep, 0);
    node_kernel<<<(Bc*Lc)/4, 128>>>(xyz, node_w, node_b, ln_ng, ln_nb, out_node);

    // s2: edge b0 (needs knn b0 + prep)
    cudaStreamWaitEvent(s2, evK0, 0);
    cudaStreamWaitEvent(s2, evPrep, 0);
    edge_kernel<<<dim3(Lc/2, 1), 128, 0, s2>>>(xyz, edge_b, ln_eg, ln_eb, out_edge, 0);

    // s1: edge b1 (needs knn b1 [same stream] + prep)
    cudaStreamWaitEvent(s1, evPrep, 0);
    edge_kernel<<<dim3(Lc/2, 1), 128, 0, s1>>>(xyz, edge_b, ln_eg, ln_eb, out_edge, 1);

    // join both side streams back to stream 0
    cudaEventRecord(evJoin1, s1);
    cudaStreamWaitEvent(0, evJoin1, 0);
    cudaEventRecord(evJoin2, s2);
    cudaStreamWaitEvent(0, evJoin2, 0);
}